// round 6
// baseline (speedup 1.0000x reference)
#include <cuda_runtime.h>
#include <math.h>
#include <stdint.h>

#define NN 50000
#define EE 500000

// node-space tables
__device__ __align__(16) float4 g_q[NN * 32];
__device__ __align__(16) float4 g_k[NN * 32];
__device__ __align__(16) float4 g_v[NN * 32];
__device__ __align__(16) float4 g_z[NN * 96];      // [n][2][192] flat [n][384]
// per-dst aggregates (written once by k_edge2)
__device__ __align__(16) float4 g_aggT[NN * 32];   // [n][2][64]   sum w*enc
__device__ __align__(16) float4 g_aggM[NN * 64];   // [n][2][128]  sum w*msg
__device__ __align__(16) float4 g_aggV[NN * 32];   // [n][2][64]   sum w*v[src]
__device__ __align__(8)  float2 g_asum[NN];        // [n][2]       sum w
__device__ int g_is64;
// combined tf32-split weights: cols [q(0) k(128) v(256) skip(384) z(512..895)]
__device__ __align__(16) float g_Whi[128 * 896];
__device__ __align__(16) float g_Wlo[128 * 896];
__device__ __align__(16) float g_ball[896];
// counting-sort scratch
__device__ int g_cnt[NN];
__device__ int g_offA[NN];
__device__ int g_bsum[128];
__device__ int g_bpre[128];
__device__ int g_off[NN + 1];
__device__ int g_pos[NN];
__device__ int g_eid[EE];

static __device__ __forceinline__ float dot4(float4 a, float4 b) {
    return a.x * b.x + a.y * b.y + a.z * b.z + a.w * b.w;
}
static __device__ __forceinline__ uint32_t f2tf(float x) {
    uint32_t r;
    asm("cvt.rna.tf32.f32 %0, %1;" : "=r"(r) : "f"(x));
    return r;
}
static __device__ __forceinline__ void mma_tf32(float* c, const uint32_t* a, const uint32_t* b) {
    asm volatile(
        "mma.sync.aligned.m16n8k8.row.col.f32.tf32.tf32.f32 "
        "{%0,%1,%2,%3},{%4,%5,%6,%7},{%8,%9},{%0,%1,%2,%3};"
        : "+f"(c[0]), "+f"(c[1]), "+f"(c[2]), "+f"(c[3])
        : "r"(a[0]), "r"(a[1]), "r"(a[2]), "r"(a[3]), "r"(b[0]), "r"(b[1]));
}

// ---------------------------------------------------------------------------
__global__ void k_detect(const int* __restrict__ ei32) {
    int odd_or = 0;
    #pragma unroll
    for (int i = 1; i < 64; i += 2) odd_or |= ei32[i];
    g_is64 = (odd_or == 0) ? 1 : 0;
}

// ---------------------------------------------------------------------------
// Kp: build combined weights [128][896] split into tf32 hi/lo, + bias [896].
// cols 0..511: Wq,Wk,Wv,Ws. cols 512..895: Zw[j,h*192+d]=sum_c Wq[j,hc]We[d,hc]
// ---------------------------------------------------------------------------
__global__ void k_prep(const float* __restrict__ Wq, const float* __restrict__ bq,
                       const float* __restrict__ Wk, const float* __restrict__ bk,
                       const float* __restrict__ Wv, const float* __restrict__ bv,
                       const float* __restrict__ Ws, const float* __restrict__ bs,
                       const float* __restrict__ We)
{
    int u = blockIdx.x * 256 + threadIdx.x;
    if (u < 128 * 896) {
        int j = u / 896, c = u % 896;
        float w;
        if (c < 512) {
            const float* src = (c < 128) ? Wq : (c < 256) ? Wk : (c < 384) ? Wv : Ws;
            w = src[j * 128 + (c & 127)];
        } else {
            int col = c - 512;
            int h = col / 192, d = col % 192;
            const float4* a = (const float4*)(Wq + j * 128 + h * 64);
            const float4* b = (const float4*)(We + d * 128 + h * 64);
            float acc = 0.f;
            #pragma unroll
            for (int cc = 0; cc < 16; cc++) acc += dot4(a[cc], b[cc]);
            w = acc;
        }
        float hi = __uint_as_float(f2tf(w));
        g_Whi[u] = hi;
        g_Wlo[u] = __uint_as_float(f2tf(w - hi));
    } else if (u < 128 * 896 + 896) {
        int c = u - 128 * 896;
        if (c < 512) {
            const float* src = (c < 128) ? bq : (c < 256) ? bk : (c < 384) ? bv : bs;
            g_ball[c] = src[c & 127];
        } else {
            int col = c - 512;
            int h = col / 192, d = col % 192;
            const float4* a = (const float4*)(bq + h * 64);
            const float4* b = (const float4*)(We + d * 128 + h * 64);
            float acc = 0.f;
            #pragma unroll
            for (int cc = 0; cc < 16; cc++) acc += dot4(a[cc], b[cc]);
            g_ball[c] = acc;
        }
    }
}

// ---------------------------------------------------------------------------
// K1: node GEMM [50000,128] @ [128,896] via 3xTF32 mma.sync (m16n8k8).
// Block 128x128, 8 warps (4m x 2n), warp tile 32x64. k-panels of 32.
// ---------------------------------------------------------------------------
__global__ void __launch_bounds__(256)
k_gemm(const float* __restrict__ x, float* __restrict__ out)
{
    extern __shared__ float sm[];
    float* xs_hi = sm;                   // [128][36]
    float* xs_lo = xs_hi + 128 * 36;
    float* ws_hi = xs_lo + 128 * 36;     // [32][136]
    float* ws_lo = ws_hi + 32 * 136;

    const int t = threadIdx.x;
    const int y = blockIdx.y;
    const int col0 = y * 128;

    float* dptr; int ds; int dcol0 = 0;
    if      (y == 0) { dptr = (float*)g_q; ds = 128; }
    else if (y == 1) { dptr = (float*)g_k; ds = 128; }
    else if (y == 2) { dptr = (float*)g_v; ds = 128; }
    else if (y == 3) { dptr = out;         ds = 128; }
    else { dptr = (float*)g_z; ds = 384; dcol0 = (y - 4) * 128; }

    const int m0 = blockIdx.x * 128;
    const int warp = t >> 5, lane = t & 31;
    const int wm = (warp >> 1) * 32;
    const int wn = (warp & 1) * 64;
    const int lr = lane >> 2;   // 0..7
    const int lc = lane & 3;    // 0..3

    float c[2][8][4];
    #pragma unroll
    for (int ma = 0; ma < 2; ma++)
        #pragma unroll
        for (int na = 0; na < 8; na++)
            #pragma unroll
            for (int i = 0; i < 4; i++) c[ma][na][i] = 0.f;

    const float4* x4 = (const float4*)x;
    for (int k0 = 0; k0 < 128; k0 += 32) {
        #pragma unroll
        for (int i = t; i < 1024; i += 256) {
            int m = i >> 3, c4 = i & 7;
            int node = m0 + m;
            float4 v = (node < NN) ? x4[(size_t)node * 32 + (k0 >> 2) + c4]
                                   : make_float4(0.f, 0.f, 0.f, 0.f);
            int kk = m * 36 + c4 * 4;
            float h0 = __uint_as_float(f2tf(v.x));
            float h1 = __uint_as_float(f2tf(v.y));
            float h2 = __uint_as_float(f2tf(v.z));
            float h3 = __uint_as_float(f2tf(v.w));
            xs_hi[kk + 0] = h0; xs_lo[kk + 0] = __uint_as_float(f2tf(v.x - h0));
            xs_hi[kk + 1] = h1; xs_lo[kk + 1] = __uint_as_float(f2tf(v.y - h1));
            xs_hi[kk + 2] = h2; xs_lo[kk + 2] = __uint_as_float(f2tf(v.z - h2));
            xs_hi[kk + 3] = h3; xs_lo[kk + 3] = __uint_as_float(f2tf(v.w - h3));
        }
        #pragma unroll
        for (int i = t; i < 1024; i += 256) {
            int kk = i >> 5, c4 = (i & 31) * 4;
            size_t gi = (size_t)(k0 + kk) * 896 + col0 + c4;
            *(float4*)&ws_hi[kk * 136 + c4] = *(const float4*)&g_Whi[gi];
            *(float4*)&ws_lo[kk * 136 + c4] = *(const float4*)&g_Wlo[gi];
        }
        __syncthreads();

        #pragma unroll
        for (int k8 = 0; k8 < 32; k8 += 8) {
            uint32_t ah[2][4], al[2][4];
            #pragma unroll
            for (int ma = 0; ma < 2; ma++) {
                int r0 = (wm + ma * 16 + lr) * 36 + k8 + lc;
                int r1 = r0 + 8 * 36;
                ah[ma][0] = __float_as_uint(xs_hi[r0]);
                ah[ma][1] = __float_as_uint(xs_hi[r1]);
                ah[ma][2] = __float_as_uint(xs_hi[r0 + 4]);
                ah[ma][3] = __float_as_uint(xs_hi[r1 + 4]);
                al[ma][0] = __float_as_uint(xs_lo[r0]);
                al[ma][1] = __float_as_uint(xs_lo[r1]);
                al[ma][2] = __float_as_uint(xs_lo[r0 + 4]);
                al[ma][3] = __float_as_uint(xs_lo[r1 + 4]);
            }
            #pragma unroll
            for (int na = 0; na < 8; na++) {
                int q0 = (k8 + lc) * 136 + wn + na * 8 + lr;
                int q1 = q0 + 4 * 136;
                uint32_t bh[2], bl[2];
                bh[0] = __float_as_uint(ws_hi[q0]);
                bh[1] = __float_as_uint(ws_hi[q1]);
                bl[0] = __float_as_uint(ws_lo[q0]);
                bl[1] = __float_as_uint(ws_lo[q1]);
                mma_tf32(c[0][na], ah[0], bh);
                mma_tf32(c[1][na], ah[1], bh);
                mma_tf32(c[0][na], al[0], bh);
                mma_tf32(c[1][na], al[1], bh);
                mma_tf32(c[0][na], ah[0], bl);
                mma_tf32(c[1][na], ah[1], bl);
            }
        }
        __syncthreads();
    }

    // epilogue: c0,c1 -> (row lr, col 2lc/2lc+1); c2,c3 -> row lr+8
    #pragma unroll
    for (int ma = 0; ma < 2; ma++) {
        #pragma unroll
        for (int na = 0; na < 8; na++) {
            int colA = wn + na * 8 + lc * 2;
            float b0 = g_ball[col0 + colA];
            float b1 = g_ball[col0 + colA + 1];
            int r0 = m0 + wm + ma * 16 + lr;
            int r1 = r0 + 8;
            if (r0 < NN) {
                float* p = dptr + (size_t)r0 * ds + dcol0 + colA;
                p[0] = c[ma][na][0] + b0;
                p[1] = c[ma][na][1] + b1;
            }
            if (r1 < NN) {
                float* p = dptr + (size_t)r1 * ds + dcol0 + colA;
                p[0] = c[ma][na][2] + b0;
                p[1] = c[ma][na][3] + b1;
            }
        }
    }
}

// ---------------------------------------------------------------------------
// Counting sort by dst
// ---------------------------------------------------------------------------
__global__ void k_hist(const void* __restrict__ ei) {
    const int e = blockIdx.x * 256 + threadIdx.x;
    if (e >= EE) return;
    int dst = g_is64 ? (int)((const long long*)ei)[EE + e] : ((const int*)ei)[EE + e];
    atomicAdd(&g_cnt[dst], 1);
}

__global__ void k_scanA() {
    __shared__ int s[512];
    const int tid = threadIdx.x;
    const int i = blockIdx.x * 512 + tid;
    int c = (i < NN) ? g_cnt[i] : 0;
    s[tid] = c;
    __syncthreads();
    #pragma unroll
    for (int o = 1; o < 512; o <<= 1) {
        int v = (tid >= o) ? s[tid - o] : 0;
        __syncthreads();
        if (tid >= o) s[tid] += v;
        __syncthreads();
    }
    if (i < NN) g_offA[i] = s[tid] - c;
    if (tid == 511) g_bsum[blockIdx.x] = s[511];
}

__global__ void k_scanB(int nchunks) {
    if (threadIdx.x == 0) {
        int run = 0;
        for (int b = 0; b < nchunks; b++) { g_bpre[b] = run; run += g_bsum[b]; }
        g_off[NN] = EE;
    }
}

__global__ void k_scanC() {
    const int i = blockIdx.x * 512 + threadIdx.x;
    if (i < NN) {
        int v = g_offA[i] + g_bpre[blockIdx.x];
        g_off[i] = v;
        g_pos[i] = v;
    }
}

__global__ void k_scatter(const void* __restrict__ ei) {
    const int e = blockIdx.x * 256 + threadIdx.x;
    if (e >= EE) return;
    int dst = g_is64 ? (int)((const long long*)ei)[EE + e] : ((const int*)ei)[EE + e];
    int p = atomicAdd(&g_pos[dst], 1);
    g_eid[p] = e;
}

// ---------------------------------------------------------------------------
// K2: warp per dst segment, lane-batched edge prefetch (MLP=32), register
// accumulation, single write.
// ---------------------------------------------------------------------------
__global__ void __launch_bounds__(256)
k_edge2(const void* __restrict__ ei,
        const float* __restrict__ tt,
        const float* __restrict__ lu,
        const float4* __restrict__ msg4,
        const float* __restrict__ tw,
        const float* __restrict__ tb)
{
    const int w = threadIdx.x >> 5, lane = threadIdx.x & 31;
    const int dst = blockIdx.x * 8 + w;
    if (dst >= NN) return;
    const int is64 = g_is64;
    const int beg = g_off[dst], end = g_off[dst + 1];

    const int lq = lane & 15;
    const float4 tw4 = ((const float4*)tw)[lq];
    const float4 tb4 = ((const float4*)tb)[lq];
    const float4 q4 = g_q[(size_t)dst * 32 + lane];
    const size_t zb0 = (size_t)dst * 96;
    const float4 za = g_z[zb0 + lane];
    const float4 zb = g_z[zb0 + 32 + lane];
    const float4 zc = g_z[zb0 + 64 + lane];

    float4 aT = make_float4(0.f, 0.f, 0.f, 0.f), aV = aT, aM0 = aT, aM1 = aT;
    float s0 = 0.f, s1 = 0.f;

    for (int base = beg; base < end; base += 32) {
        const int cnt = min(32, end - base);
        int eidl = 0, srcl = 0; float rell = 0.f;
        if (lane < cnt) {
            eidl = g_eid[base + lane];
            long long s = is64 ? ((const long long*)ei)[eidl]
                               : (long long)((const int*)ei)[eidl];
            srcl = (int)s;
            rell = tt[eidl] - lu[s];
        }

        for (int j = 0; j < cnt; j++) {
            const int eid = __shfl_sync(0xffffffffu, eidl, j);
            const int src = __shfl_sync(0xffffffffu, srcl, j);
            const float rel = __shfl_sync(0xffffffffu, rell, j);

            const size_t mb = (size_t)eid * 32;
            float4 k4 = g_k[(size_t)src * 32 + lane];
            float4 v4 = g_v[(size_t)src * 32 + lane];
            float4 m4 = msg4[mb + lane];

            float4 ev;
            ev.x = __cosf(rel * tw4.x + tb4.x);
            ev.y = __cosf(rel * tw4.y + tb4.y);
            ev.z = __cosf(rel * tw4.z + tb4.z);
            ev.w = __cosf(rel * tw4.w + tb4.w);

            float qk = dot4(q4, k4);
            float4 Aa = (lane < 16) ? ev : msg4[mb + lane - 16];
            float4 Ab = (lane < 16) ? msg4[mb + lane + 16] : ev;
            float pb = dot4(zb, Ab) + qk;
            float p0 = dot4(za, Aa) + ((lane < 16) ? pb : 0.f);
            float p1 = dot4(zc, m4) + ((lane < 16) ? 0.f : pb);
            #pragma unroll
            for (int o = 16; o >= 1; o >>= 1) {
                p0 += __shfl_xor_sync(0xffffffffu, p0, o);
                p1 += __shfl_xor_sync(0xffffffffu, p1, o);
            }

            float w0 = __expf(0.125f * p0);
            float w1 = __expf(0.125f * p1);

            float sc = (lane < 16) ? w0 : w1;
            aT.x += sc * ev.x; aT.y += sc * ev.y; aT.z += sc * ev.z; aT.w += sc * ev.w;
            aV.x += sc * v4.x; aV.y += sc * v4.y; aV.z += sc * v4.z; aV.w += sc * v4.w;
            aM0.x += w0 * m4.x; aM0.y += w0 * m4.y; aM0.z += w0 * m4.z; aM0.w += w0 * m4.w;
            aM1.x += w1 * m4.x; aM1.y += w1 * m4.y; aM1.z += w1 * m4.z; aM1.w += w1 * m4.w;
            s0 += w0; s1 += w1;
        }
    }

    g_aggT[(size_t)dst * 32 + lane] = aT;
    g_aggV[(size_t)dst * 32 + lane] = aV;
    g_aggM[(size_t)dst * 64 + lane]      = aM0;
    g_aggM[(size_t)dst * 64 + 32 + lane] = aM1;
    if (lane == 0) g_asum[dst] = make_float2(s0, s1);
}

// ---------------------------------------------------------------------------
// K3: out[n,h,c] += (aggV[n,h,c] + sum_d aggE[n,h,d]*We[d,h*64+c]) / asum[n,h]
// ---------------------------------------------------------------------------
__global__ void k_final(const float* __restrict__ We, float* __restrict__ out)
{
    extern __shared__ float sm[];
    float* WeS = sm;                 // 192 x 132
    float* sA  = sm + 192 * 132;     // 4 x 392
    float* sS  = sA + 4 * 392;       // 8 asums
    const int t = threadIdx.x;       // 128

    const float4* We4 = (const float4*)We;
    for (int i = t; i < 192 * 32; i += 128) {
        int d = i >> 5, c4 = i & 31;
        ((float4*)(WeS + d * 132))[c4] = We4[i];
    }

    const int j = t, h = t >> 6;
    for (int q0 = blockIdx.x * 4; q0 < NN; q0 += gridDim.x * 4) {
        __syncthreads();
        for (int i = t; i < 4 * 96; i += 128) {
            int ni = i / 96, m = i % 96;
            int node = q0 + ni;
            int hh = m / 48, d4 = m % 48;
            float4 val = (d4 < 16) ? g_aggT[(size_t)node * 32 + hh * 16 + d4]
                                   : g_aggM[(size_t)node * 64 + hh * 32 + (d4 - 16)];
            *(float4*)&sA[ni * 392 + hh * 196 + d4 * 4] = val;
        }
        if (t < 8) sS[t] = ((const float*)g_asum)[(size_t)(q0 + (t >> 1)) * 2 + (t & 1)];
        __syncthreads();

        float acc0 = 0.f, acc1 = 0.f, acc2 = 0.f, acc3 = 0.f;
        const float* a0 = sA + 0 * 392 + h * 196;
        const float* a1 = sA + 1 * 392 + h * 196;
        const float* a2 = sA + 2 * 392 + h * 196;
        const float* a3 = sA + 3 * 392 + h * 196;
        #pragma unroll 4
        for (int d = 0; d < 192; d++) {
            float wv = WeS[d * 132 + j];
            acc0 += wv * a0[d];
            acc1 += wv * a1[d];
            acc2 += wv * a2[d];
            acc3 += wv * a3[d];
        }

        const float* gv = (const float*)g_aggV;
        size_t n0 = (size_t)q0;
        out[(n0 + 0) * 128 + j] += (gv[(n0 + 0) * 128 + j] + acc0) * (1.f / (sS[0 + h] + 1e-16f));
        out[(n0 + 1) * 128 + j] += (gv[(n0 + 1) * 128 + j] + acc1) * (1.f / (sS[2 + h] + 1e-16f));
        out[(n0 + 2) * 128 + j] += (gv[(n0 + 2) * 128 + j] + acc2) * (1.f / (sS[4 + h] + 1e-16f));
        out[(n0 + 3) * 128 + j] += (gv[(n0 + 3) * 128 + j] + acc3) * (1.f / (sS[6 + h] + 1e-16f));
    }
}

// ---------------------------------------------------------------------------
extern "C" void kernel_launch(void* const* d_in, const int* in_sizes, int n_in,
                              void* d_out, int out_size)
{
    const float* x  = (const float*)d_in[0];
    const float* lu = (const float*)d_in[1];
    const float* tt = (const float*)d_in[2];
    const float* msg = (const float*)d_in[3];
    const float* tw = (const float*)d_in[4];
    const float* tb = (const float*)d_in[5];
    const float* Wq = (const float*)d_in[6];
    const float* bq = (const float*)d_in[7];
    const float* Wk = (const float*)d_in[8];
    const float* bk = (const float*)d_in[9];
    const float* Wv = (const float*)d_in[10];
    const float* bv = (const float*)d_in[11];
    const float* We = (const float*)d_in[12];
    const float* Ws = (const float*)d_in[13];
    const float* bs = (const float*)d_in[14];
    const void* ei  = d_in[15];
    float* out = (float*)d_out;

    const int GEMM_SMEM = (2 * 128 * 36 + 2 * 32 * 136) * 4;  // 71680
    cudaFuncSetAttribute(k_gemm,  cudaFuncAttributeMaxDynamicSharedMemorySize, GEMM_SMEM);
    cudaFuncSetAttribute(k_final, cudaFuncAttributeMaxDynamicSharedMemorySize, 107680);

    void* pcnt;
    cudaGetSymbolAddress(&pcnt, g_cnt);
    cudaMemsetAsync(pcnt, 0, NN * sizeof(int));

    const int NCHUNK = (NN + 511) / 512;   // 98

    k_detect<<<1, 1>>>((const int*)ei);
    k_prep<<<452, 256>>>(Wq, bq, Wk, bk, Wv, bv, Ws, bs, We);
    k_gemm<<<dim3(391, 7, 1), 256, GEMM_SMEM>>>(x, out);
    k_hist<<<(EE + 255) / 256, 256>>>(ei);
    k_scanA<<<NCHUNK, 512>>>();
    k_scanB<<<1, 32>>>(NCHUNK);
    k_scanC<<<NCHUNK, 512>>>();
    k_scatter<<<(EE + 255) / 256, 256>>>(ei);
    k_edge2<<<(NN + 7) / 8, 256>>>(ei, tt, lu, (const float4*)msg, tw, tb);
    k_final<<<592, 128, 107680>>>(We, out);
}